// round 16
// baseline (speedup 1.0000x reference)
#include <cuda_runtime.h>
#include <math.h>
#include <stdint.h>

#define B_   2
#define T_   2048
#define E_   1024
#define H_   16
#define HD_  64
#define L_   4
#define V_   32000
#define F_   4096
#define BT_  (B_*T_)
#define QS_  (3*E_)
#define EPS_ 1e-5f

// ---------------- device scratch ----------------
__device__ float g_x  [BT_*E_];
__device__ float g_h  [BT_*E_];
__device__ float g_a  [BT_*E_];
__device__ float g_qkv[(size_t)BT_*QS_];
__device__ float g_ff [(size_t)BT_*F_];
__device__ float g_wqkv[(size_t)E_*QS_];
__device__ float g_logits[(size_t)BT_*V_];
__device__ float g_rowloss[BT_];
__device__ float g_loss_dummy[1];

// ---------------- helpers ----------------
__device__ __forceinline__ uint32_t smem_u32(const void* p) {
    uint32_t a;
    asm("{ .reg .u64 t; cvta.to.shared.u64 t, %1; cvt.u32.u64 %0, t; }" : "=r"(a) : "l"(p));
    return a;
}
__device__ __forceinline__ float rna(float x) {
    float r; asm("cvt.rna.tf32.f32 %0, %1;" : "=f"(r) : "f"(x)); return r;
}
__device__ __forceinline__ uint32_t rna_u(uint32_t x) {
    uint32_t r; asm("cvt.rna.tf32.f32 %0, %1;" : "=r"(r) : "r"(x)); return r;
}
#define CP_ASYNC16(saddr, gptr) \
    asm volatile("cp.async.cg.shared.global [%0], [%1], 16;" :: "r"(saddr), "l"(gptr))
#define CP_COMMIT() asm volatile("cp.async.commit_group;")
#define CP_WAIT1()  asm volatile("cp.async.wait_group 1;")
#define CP_WAIT0()  asm volatile("cp.async.wait_group 0;")

__device__ __forceinline__ void mma_tf32(float* d, const uint32_t* a, const uint32_t* b) {
    asm volatile("mma.sync.aligned.m16n8k8.row.col.f32.tf32.tf32.f32 "
        "{%0,%1,%2,%3}, {%4,%5,%6,%7}, {%8,%9}, {%0,%1,%2,%3};"
        : "+f"(d[0]), "+f"(d[1]), "+f"(d[2]), "+f"(d[3])
        : "r"(a[0]), "r"(a[1]), "r"(a[2]), "r"(a[3]), "r"(b[0]), "r"(b[1]));
}

// ---------------- embedding ----------------
__global__ void embed_k(const int* __restrict__ idx, const float* __restrict__ tok,
                        const float* __restrict__ pos, float* __restrict__ x) {
    int i = blockIdx.x * blockDim.x + threadIdx.x;
    if (i >= BT_ * E_) return;
    int e = i & (E_-1); int bt = i >> 10; int t = bt & (T_-1);
    x[i] = tok[(size_t)idx[bt]*E_ + e] + pos[(size_t)t*E_ + e];
}

// ---------------- layernorm (rna output: feeds GEMM A) ----------------
__global__ void ln_k(const float* __restrict__ x, const float* __restrict__ g,
                     const float* __restrict__ b, float* __restrict__ out) {
    __shared__ float red[256];
    int row = blockIdx.x, tid = threadIdx.x;
    const float* xr = x + (size_t)row * E_;
    float s = 0.f;
    for (int e = tid; e < E_; e += 256) s += xr[e];
    red[tid] = s; __syncthreads();
    for (int k = 128; k > 0; k >>= 1) { if (tid < k) red[tid] += red[tid+k]; __syncthreads(); }
    float mean = red[0] * (1.f/E_); __syncthreads();
    float vs = 0.f;
    for (int e = tid; e < E_; e += 256) { float d = xr[e]-mean; vs += d*d; }
    red[tid] = vs; __syncthreads();
    for (int k = 128; k > 0; k >>= 1) { if (tid < k) red[tid] += red[tid+k]; __syncthreads(); }
    float inv = rsqrtf(red[0]*(1.f/E_) + EPS_);
    float* orow = out + (size_t)row * E_;
    for (int e = tid; e < E_; e += 256)
        orow[e] = rna((xr[e]-mean)*inv*g[e] + b[e]);
}

// ---------------- pack QKV weights: [H,E,HD]x3 -> [E, 3*E] row-major (+rna) ----------------
__global__ void pack_qkv(const float* __restrict__ Wq, const float* __restrict__ Wk,
                         const float* __restrict__ Wv, int l, float* __restrict__ out) {
    int i = blockIdx.x * blockDim.x + threadIdx.x;
    if (i >= E_ * E_) return;
    int e = i >> 10, n = i & (E_-1);
    int h = n >> 6, d = n & (HD_-1);
    size_t src = (((size_t)l * H_ + h) * E_ + e) * HD_ + d;
    size_t o = (size_t)e * QS_ + n;
    out[o]        = rna(Wq[src]);
    out[o + E_]   = rna(Wk[src]);
    out[o + 2*E_] = rna(Wv[src]);
}

// ---------------- tf32 mma.sync GEMM: C[M,N] = A[M,K] @ B[K,N] ----------------
// CTA tile 256x128 (MxN), 256 threads = 8 warps (4M x 2N), warp tile 64x64,
// BK=32, 3-stage cp.async pipeline, single sync per K-iter.
// Requires M%256==0, N%128==0, K%32==0.
#define ASTR 36
#define BSTR 136
#define NSTG 3
#define ASTEP (256*ASTR)        // floats per A stage
#define BSTEP (32*BSTR)         // floats per B stage
#define GEMM_SMEM (NSTG*(ASTEP+BSTEP)*4)   // 162816 B
template<bool BIAS, bool RES, bool RELU, bool RNAO>
__global__ void __launch_bounds__(256)
gemm_mma(const float* __restrict__ A, const float* __restrict__ Bm,
         const float* __restrict__ bias, const float* __restrict__ res,
         float* __restrict__ C, int M, int N, int K) {
    extern __shared__ float smf[];
    float* As = smf;                 // [3][256][36]
    float* Bs = smf + NSTG*ASTEP;    // [3][32][136]
    const int tid = threadIdx.x;
    const int wid = tid >> 5, lane = tid & 31;
    const int lr = lane >> 2, lc = lane & 3;
    const int warp_m = wid & 3, warp_n = wid >> 2;
    const int m0 = blockIdx.y * 256, n0 = blockIdx.x * 128;

    // A loads: one row per thread, 8x 16B chunks (32 floats)
    const float* Ag = A + (size_t)(m0 + tid) * K;
    const uint32_t sA = smem_u32(As) + (uint32_t)(tid * ASTR) * 4u;
    // B loads: thread -> (k=tid>>3, 16 floats at (tid&7)*16)
    const int brow = tid >> 3, bcol = (tid & 7) * 16;
    const float* Bg = Bm + (size_t)brow * N + n0 + bcol;
    const uint32_t sB = smem_u32(Bs) + (uint32_t)(brow * BSTR + bcol) * 4u;

    float acc[4][8][4];
#pragma unroll
    for (int i = 0; i < 4; i++)
#pragma unroll
        for (int j = 0; j < 8; j++)
#pragma unroll
            for (int r = 0; r < 4; r++) acc[i][j][r] = 0.f;

    const int nk = K >> 5;

#define LOAD_TILE(IT) do {                                              \
        const int _st = (IT) % NSTG;                                    \
        const float* _ap = Ag + (IT) * 32;                              \
        const float* _bp = Bg + (size_t)((IT) * 32) * N;                \
        const uint32_t _sa = sA + (uint32_t)(_st * ASTEP) * 4u;         \
        const uint32_t _sb = sB + (uint32_t)(_st * BSTEP) * 4u;         \
        _Pragma("unroll")                                               \
        for (int _j = 0; _j < 8; _j++) CP_ASYNC16(_sa + _j*16u, _ap + _j*4); \
        _Pragma("unroll")                                               \
        for (int _j = 0; _j < 4; _j++) CP_ASYNC16(_sb + _j*16u, _bp + _j*4); \
        CP_COMMIT();                                                    \
    } while (0)

    LOAD_TILE(0);
    if (nk > 1) LOAD_TILE(1);

    for (int it = 0; it < nk; it++) {
        if (it + 1 < nk) { CP_WAIT1(); } else { CP_WAIT0(); }
        __syncthreads();
        if (it + 2 < nk) LOAD_TILE(it + 2);

        const int st = it % NSTG;
        const uint32_t* Ab = (const uint32_t*)(As + st*ASTEP + (warp_m*64)*ASTR);
        const uint32_t* Bb = (const uint32_t*)(Bs + st*BSTEP) + warp_n*64;
#pragma unroll
        for (int kk = 0; kk < 4; kk++) {
            const int k0 = kk * 8;
            uint32_t afr[4][4], bfr[8][2];
#pragma unroll
            for (int mt = 0; mt < 4; mt++) {
                int r = mt*16 + lr;
                afr[mt][0] = Ab[(size_t)r     * ASTR + k0 + lc];
                afr[mt][1] = Ab[(size_t)(r+8) * ASTR + k0 + lc];
                afr[mt][2] = Ab[(size_t)r     * ASTR + k0 + lc + 4];
                afr[mt][3] = Ab[(size_t)(r+8) * ASTR + k0 + lc + 4];
            }
#pragma unroll
            for (int nt = 0; nt < 8; nt++) {
                bfr[nt][0] = rna_u(Bb[(size_t)(k0 + lc)     * BSTR + nt*8 + lr]);
                bfr[nt][1] = rna_u(Bb[(size_t)(k0 + lc + 4) * BSTR + nt*8 + lr]);
            }
#pragma unroll
            for (int mt = 0; mt < 4; mt++)
#pragma unroll
                for (int nt = 0; nt < 8; nt++)
                    mma_tf32(acc[mt][nt], afr[mt], bfr[nt]);
        }
    }
#undef LOAD_TILE

    // epilogue
#pragma unroll
    for (int mt = 0; mt < 4; mt++) {
        int r0 = m0 + warp_m*64 + mt*16 + lr;
#pragma unroll
        for (int nt = 0; nt < 8; nt++) {
            int col = n0 + warp_n*64 + nt*8 + lc*2;
            float b0 = 0.f, b1 = 0.f;
            if (BIAS) { b0 = bias[col]; b1 = bias[col+1]; }
#pragma unroll
            for (int half = 0; half < 2; half++) {
                int r = r0 + half*8;
                float c0 = acc[mt][nt][half*2+0] + b0;
                float c1 = acc[mt][nt][half*2+1] + b1;
                float* cp = C + (size_t)r * N + col;
                if (RES) {
                    const float* rp = res + (size_t)r * N + col;
                    c0 += rp[0]; c1 += rp[1];
                }
                if (RELU) { c0 = fmaxf(c0, 0.f); c1 = fmaxf(c1, 0.f); }
                if (RNAO) { c0 = rna(c0); c1 = rna(c1); }
                *(float2*)cp = make_float2(c0, c1);
            }
        }
    }
}

// ---------------- flash-tiled causal attention (64-query tile) ----------------
// q,k,v packed in qkv[BT, 3E]: q at +0, k at +E, v at +2E, head h at h*64.
#define ATTN_SMEM 53504
__global__ void __launch_bounds__(256)
attn_flash(const float* __restrict__ qkv, float* __restrict__ o) {
    extern __shared__ float sm[];
    float* Ks = sm;                 // [64][68]
    float* Vs = sm + 64*68;         // [64][68]
    float* Ss = sm + 2*64*68;       // [64][65]
    float* redm = Ss + 64*65;       // [4][64]
    float* redl = redm + 256;       // [4][64]
    int tid = threadIdx.x;
    int i = tid & 63, jg = tid >> 6;
    int qt = blockIdx.x, h = blockIdx.y, b = blockIdx.z;
    size_t rowb = (size_t)b * T_;
    size_t hoff = h * 64;

    { // stage Q through Ks
        int j = tid >> 2, seg = tid & 3;
        const float4* qr = (const float4*)(qkv + (rowb + qt*64 + j) * QS_ + hoff);
        float4* dst = (float4*)(Ks + j*68);
#pragma unroll
        for (int t4 = 0; t4 < 4; t4++) dst[seg*4 + t4] = qr[seg*4 + t4];
    }
    __syncthreads();
    float qreg[64];
    {
        const float4* src = (const float4*)(Ks + i*68);
#pragma unroll
        for (int d4 = 0; d4 < 16; d4++) {
            float4 t4 = src[d4];
            qreg[d4*4+0] = t4.x*0.125f; qreg[d4*4+1] = t4.y*0.125f;
            qreg[d4*4+2] = t4.z*0.125f; qreg[d4*4+3] = t4.w*0.125f;
        }
    }
    __syncthreads();

    float acc[16];
#pragma unroll
    for (int d = 0; d < 16; d++) acc[d] = 0.f;
    float mi = -1e30f, li = 0.f;

    for (int st = 0; st <= qt; st++) {
        {
            int j = tid >> 2, seg = tid & 3;
            size_t rb = (rowb + st*64 + j) * QS_ + hoff;
            const float4* kr = (const float4*)(qkv + rb + E_);
            const float4* vr = (const float4*)(qkv + rb + 2*E_);
            float4* kd = (float4*)(Ks + j*68);
            float4* vd = (float4*)(Vs + j*68);
#pragma unroll
            for (int t4 = 0; t4 < 4; t4++) { kd[seg*4+t4] = kr[seg*4+t4]; vd[seg*4+t4] = vr[seg*4+t4]; }
        }
        __syncthreads();

        float sreg[16];
        float lm = -1e30f;
        bool diag = (st == qt);
#pragma unroll
        for (int jj = 0; jj < 16; jj++) {
            int j = jg*16 + jj;
            const float4* kr = (const float4*)(Ks + j*68);
            float s = 0.f;
#pragma unroll
            for (int d4 = 0; d4 < 16; d4++) {
                float4 kv = kr[d4];
                s += qreg[d4*4+0]*kv.x + qreg[d4*4+1]*kv.y + qreg[d4*4+2]*kv.z + qreg[d4*4+3]*kv.w;
            }
            if (diag && j > i) s = -1e30f;
            sreg[jj] = s;
            lm = fmaxf(lm, s);
        }
        redm[jg*64 + i] = lm;
        __syncthreads();
        float mt = fmaxf(fmaxf(redm[i], redm[64+i]), fmaxf(redm[128+i], redm[192+i]));
        float mnew = fmaxf(mi, mt);
        float corr = __expf(mi - mnew);
        float ls = 0.f;
#pragma unroll
        for (int jj = 0; jj < 16; jj++) {
            float p = __expf(sreg[jj] - mnew);
            Ss[i*65 + jg*16 + jj] = p;
            ls += p;
        }
        redl[jg*64 + i] = ls;
        __syncthreads();
        li = li*corr + redl[i] + redl[64+i] + redl[128+i] + redl[192+i];
        mi = mnew;
#pragma unroll
        for (int d = 0; d < 16; d++) acc[d] *= corr;
        int dbase = jg*16;
        for (int j = 0; j < 64; j++) {
            float p = Ss[i*65 + j];
            const float4* vrow = (const float4*)(Vs + j*68 + dbase);
#pragma unroll
            for (int d4 = 0; d4 < 4; d4++) {
                float4 vv = vrow[d4];
                acc[d4*4+0] += p*vv.x; acc[d4*4+1] += p*vv.y;
                acc[d4*4+2] += p*vv.z; acc[d4*4+3] += p*vv.w;
            }
        }
        __syncthreads();
    }
    float inv = 1.f / li;
    float* orow = o + (rowb + qt*64 + i) * E_ + hoff + jg*16;
#pragma unroll
    for (int d4 = 0; d4 < 4; d4++) {
        float4 ov;
        ov.x = rna(acc[d4*4+0]*inv); ov.y = rna(acc[d4*4+1]*inv);
        ov.z = rna(acc[d4*4+2]*inv); ov.w = rna(acc[d4*4+3]*inv);
        *(float4*)(orow + d4*4) = ov;
    }
}

// ---------------- cross-entropy ----------------
__global__ void rowloss_k(const float* __restrict__ logits, const int* __restrict__ tgt,
                          float* __restrict__ rl) {
    __shared__ float red[256];
    int row = blockIdx.x, tid = threadIdx.x;
    const float* lr = logits + (size_t)row * V_;
    float lmax = -1e30f;
    for (int i = tid; i < V_; i += 256) lmax = fmaxf(lmax, lr[i]);
    red[tid] = lmax; __syncthreads();
    for (int k = 128; k > 0; k >>= 1) { if (tid < k) red[tid] = fmaxf(red[tid], red[tid+k]); __syncthreads(); }
    float mx = red[0]; __syncthreads();
    float s = 0.f;
    for (int i = tid; i < V_; i += 256) s += expf(lr[i] - mx);
    red[tid] = s; __syncthreads();
    for (int k = 128; k > 0; k >>= 1) { if (tid < k) red[tid] += red[tid+k]; __syncthreads(); }
    if (tid == 0) rl[row] = -(lr[tgt[row]] - mx - logf(red[0]));
}
__global__ void finloss_k(const float* __restrict__ rl, float* __restrict__ dst) {
    __shared__ float red[256];
    int tid = threadIdx.x;
    float s = 0.f;
    for (int i = tid; i < BT_; i += 256) s += rl[i];
    red[tid] = s; __syncthreads();
    for (int k = 128; k > 0; k >>= 1) { if (tid < k) red[tid] += red[tid+k]; __syncthreads(); }
    if (tid == 0) dst[0] = red[0] * (1.f/BT_);
}

// ---------------- launch ----------------
extern "C" void kernel_launch(void* const* d_in, const int* in_sizes, int n_in,
                              void* d_out, int out_size) {
    const int*   idx     = (const int*)  d_in[0];
    const int*   targets = (const int*)  d_in[1];
    const float* tok     = (const float*)d_in[2];
    const float* pos     = (const float*)d_in[3];
    const float* Wq      = (const float*)d_in[4];
    const float* Wk      = (const float*)d_in[5];
    const float* Wv      = (const float*)d_in[6];
    const float* Wproj   = (const float*)d_in[7];
    const float* bproj   = (const float*)d_in[8];
    const float* ln1g    = (const float*)d_in[9];
    const float* ln1b    = (const float*)d_in[10];
    const float* ln2g    = (const float*)d_in[11];
    const float* ln2b    = (const float*)d_in[12];
    const float* W1      = (const float*)d_in[13];
    const float* b1      = (const float*)d_in[14];
    const float* W2      = (const float*)d_in[15];
    const float* b2      = (const float*)d_in[16];
    const float* lnfg    = (const float*)d_in[17];
    const float* lnfb    = (const float*)d_in[18];
    const float* Whead   = (const float*)d_in[19];
    const float* bhead   = (const float*)d_in[20];

    float *x,*h,*a,*qkv,*ff,*wqkv,*lgs,*rl,*dummy;
    cudaGetSymbolAddress((void**)&x, g_x);     cudaGetSymbolAddress((void**)&h, g_h);
    cudaGetSymbolAddress((void**)&a, g_a);     cudaGetSymbolAddress((void**)&qkv, g_qkv);
    cudaGetSymbolAddress((void**)&ff, g_ff);   cudaGetSymbolAddress((void**)&wqkv, g_wqkv);
    cudaGetSymbolAddress((void**)&lgs, g_logits);
    cudaGetSymbolAddress((void**)&rl, g_rowloss);
    cudaGetSymbolAddress((void**)&dummy, g_loss_dummy);

    cudaFuncSetAttribute(gemm_mma<false,false,false,false>, cudaFuncAttributeMaxDynamicSharedMemorySize, GEMM_SMEM);
    cudaFuncSetAttribute(gemm_mma<true,true,false,false>,  cudaFuncAttributeMaxDynamicSharedMemorySize, GEMM_SMEM);
    cudaFuncSetAttribute(gemm_mma<true,false,true,true>,   cudaFuncAttributeMaxDynamicSharedMemorySize, GEMM_SMEM);
    cudaFuncSetAttribute(gemm_mma<true,false,false,false>, cudaFuncAttributeMaxDynamicSharedMemorySize, GEMM_SMEM);
    cudaFuncSetAttribute(attn_flash, cudaFuncAttributeMaxDynamicSharedMemorySize, ATTN_SMEM);

    float* out = (float*)d_out;
    const long long BTV = (long long)BT_ * V_;
    float* logits   = ((long long)out_size >= BTV) ? out : lgs;
    float* loss_dst = ((long long)out_size == BTV + 1) ? (out + BTV)
                    : (((long long)out_size < BTV) ? out : dummy);

    embed_k<<<(BT_*E_ + 255)/256, 256>>>(idx, tok, pos, x);

    dim3 gQKV(QS_/128, BT_/256);
    dim3 gE(E_/128, BT_/256);
    for (int l = 0; l < L_; l++) {
        ln_k<<<BT_, 256>>>(x, ln1g + l*E_, ln1b + l*E_, h);
        pack_qkv<<<(E_*E_ + 255)/256, 256>>>(Wq, Wk, Wv, l, wqkv);

        gemm_mma<false,false,false,false><<<gQKV, 256, GEMM_SMEM>>>(h, wqkv, 0, 0, qkv, BT_, QS_, E_);

        attn_flash<<<dim3(T_/64, H_, B_), 256, ATTN_SMEM>>>(qkv, a);

        gemm_mma<true,true,false,false><<<gE, 256, GEMM_SMEM>>>(
            a, Wproj + (size_t)l*E_*E_, bproj + l*E_, x, x, BT_, E_, E_);

        ln_k<<<BT_, 256>>>(x, ln2g + l*E_, ln2b + l*E_, h);

        gemm_mma<true,false,true,true><<<dim3(F_/128, BT_/256), 256, GEMM_SMEM>>>(
            h, W1 + (size_t)l*E_*F_, b1 + l*F_, 0, ff, BT_, F_, E_);

        gemm_mma<true,true,false,false><<<gE, 256, GEMM_SMEM>>>(
            ff, W2 + (size_t)l*F_*E_, b2 + l*E_, x, x, BT_, E_, F_);
    }

    ln_k<<<BT_, 256>>>(x, lnfg, lnfb, h);

    gemm_mma<true,false,false,false><<<dim3(V_/128, BT_/256), 256, GEMM_SMEM>>>(
        h, Whead, bhead, 0, logits, BT_, V_, E_);

    rowloss_k<<<BT_, 256>>>(logits, targets, rl);
    finloss_k<<<1, 256>>>(rl, loss_dst);
}